// round 11
// baseline (speedup 1.0000x reference)
#include <cuda_runtime.h>
#include <math.h>

#define NB    128
#define NPTS  128
#define DIN   1024
#define H1D   256
#define DOUT  32
#define KCL   8
#define NTRI  8128
#define BN    16384
#define DSTR  132     // D row stride in floats

__device__ float g_feats[BN * DOUT];

__device__ __forceinline__ float gelu_exact(float v) {
    return 0.5f * v * (1.0f + erff(v * 0.70710678118654752440f));
}
__device__ __forceinline__ int tri_base(int i) { return (i * (255 - i)) >> 1; }

__device__ __forceinline__ unsigned long long pack2(float v) {
    unsigned long long r;
    asm("mov.b64 %0, {%1, %1};" : "=l"(r) : "f"(v));
    return r;
}
__device__ __forceinline__ void fma2(unsigned long long& d, unsigned long long a, unsigned long long b) {
    asm("fma.rn.f32x2 %0, %1, %2, %3;" : "=l"(d) : "l"(a), "l"(b), "l"(d));
}
__device__ __forceinline__ float2 unpack2(unsigned long long v) {
    float2 r;
    asm("mov.b64 {%0, %1}, %2;" : "=f"(r.x), "=f"(r.y) : "l"(v));
    return r;
}

// ---------------------------------------------------------------------------
// MLP: 512 CTAs x 256 threads, min 3 CTAs/SM. W1 prefetched one kk ahead.
// ---------------------------------------------------------------------------
__global__ __launch_bounds__(256, 3) void mlp_kernel(
    const float* __restrict__ x,  const float* __restrict__ W1,
    const float* __restrict__ b1, const float* __restrict__ W2,
    const float* __restrict__ b2)
{
    __shared__ __align__(16) float xs[128 * 36];
    const int tid  = threadIdx.x;
    const int tok0 = blockIdx.x * 32;
    const int grp  = tid >> 7;
    const int cp   = tid & 127;

    unsigned long long acc[16];
#pragma unroll
    for (int u = 0; u < 16; u++) acc[u] = 0ull;

    for (int kc = 0; kc < DIN; kc += 128) {
        for (int idx = tid; idx < 32 * 128; idx += 256) {
            int t = idx >> 7, kk = idx & 127;
            xs[kk * 36 + t] = gelu_exact(x[(size_t)(tok0 + t) * DIN + kc + kk]);
        }
        __syncthreads();

        const float* wp = W1 + (size_t)kc * H1D + 2 * cp;
        float2 wv = *(const float2*)wp;           // prefetch kk = 0
#pragma unroll 4
        for (int kk = 0; kk < 128; kk++) {
            float2 cur = wv;
            if (kk + 1 < 128)
                wv = *(const float2*)(wp + (size_t)(kk + 1) * H1D);   // prefetch next
            unsigned long long w0 = pack2(cur.x), w1 = pack2(cur.y);
            const ulonglong2* row = (const ulonglong2*)(xs + kk * 36 + grp * 16);
#pragma unroll
            for (int v = 0; v < 4; v++) {
                ulonglong2 f = row[v];
                fma2(acc[2 * v],         f.x, w0);
                fma2(acc[2 * v + 1],     f.y, w0);
                fma2(acc[8 + 2 * v],     f.x, w1);
                fma2(acc[8 + 2 * v + 1], f.y, w1);
            }
        }
        __syncthreads();
    }

    float h0[16], h1[16];
    {
        float bb0 = b1[2 * cp], bb1 = b1[2 * cp + 1];
#pragma unroll
        for (int u = 0; u < 8; u++) {
            float2 p0 = unpack2(acc[u]);
            h0[2 * u]     = gelu_exact(p0.x + bb0);
            h0[2 * u + 1] = gelu_exact(p0.y + bb0);
            float2 p1 = unpack2(acc[8 + u]);
            h1[2 * u]     = gelu_exact(p1.x + bb1);
            h1[2 * u + 1] = gelu_exact(p1.y + bb1);
        }
    }

    float oacc[4];
#pragma unroll
    for (int u = 0; u < 4; u++) oacc[u] = b2[(u * 256 + tid) & 31];

    for (int half = 0; half < 2; half++) {
        if ((cp >> 6) == half) {
            int c0 = 2 * cp - half * 128;
#pragma unroll
            for (int t = 0; t < 16; t++) {
                xs[(grp * 16 + t) * 128 + c0]     = h0[t];
                xs[(grp * 16 + t) * 128 + c0 + 1] = h1[t];
            }
        }
        __syncthreads();
#pragma unroll
        for (int u = 0; u < 4; u++) {
            int lin = u * 256 + tid;
            int t = lin >> 5, o = lin & 31;
            float s = oacc[u];
            for (int j = 0; j < 128; j++)
                s = fmaf(xs[t * 128 + j], W2[(size_t)(half * 128 + j) * DOUT + o], s);
            oacc[u] = s;
        }
        __syncthreads();
    }
#pragma unroll
    for (int u = 0; u < 4; u++) {
        int lin = u * 256 + tid;
        int t = lin >> 5, o = lin & 31;
        g_feats[(size_t)(tok0 + t) * DOUT + o] = oacc[u];
    }
}

// ---------------------------------------------------------------------------
// Ward: 2 independent batches per CTA (256 threads = 2 x 128), named barriers
// per half. Per-half layout identical to the R10-proven design.
// ---------------------------------------------------------------------------
#define HALF_FLOATS 21680   // per-half smem block (floats), 16B-multiple
#define WARD_DYN_SMEM (2 * HALF_FLOATS * 4)

__device__ __forceinline__ unsigned long long umin64(unsigned long long a, unsigned long long b) {
    return a < b ? a : b;
}
__device__ __forceinline__ unsigned long long mkkey(float v, int row, int col) {
    return ((unsigned long long)__float_as_uint(v) << 32) |
           ((unsigned long long)row << 16) | (unsigned long long)col;
}
__device__ __forceinline__ void half_bar(int h) {
    asm volatile("bar.sync %0, 128;" :: "r"(1 + h) : "memory");
}

__global__ __launch_bounds__(256) void ward_kernel(float* __restrict__ out) {
    extern __shared__ __align__(16) float sm[];

    const int tid  = threadIdx.x;
    const int h    = tid >> 7;          // half 0/1 -> batch
    const int a    = tid & 127;         // point id
    const int b    = blockIdx.x * 2 + h;
    const int lane = tid & 31;
    const float INF = __int_as_float(0x7f800000);

    float* base  = sm + h * HALF_FLOATS;
    float* D     = base;                                   // [128*132] = 16896
    float* centT = D + NPTS * DSTR;                        // [32*128]  = 4096
    unsigned long long* Mkey = (unsigned long long*)(centT + DOUT * NPTS);  // 128 u64
    float* szs     = (float*)(Mkey + NPTS);                // [128]
    float* centNew = szs + NPTS;                           // [32]
    int*   cnt     = (int*)(centNew + DOUT);               // [2]
    int*   list    = cnt + 2;                              // [2][128]
    unsigned* sAlive = (unsigned*)(list + 2 * NPTS);       // [4]

    // ---- init ----
    for (int idx = a; idx < NPTS * DOUT; idx += 128) {
        int r = idx >> 5, d = idx & 31;
        centT[d * NPTS + r] = g_feats[(size_t)(b * NPTS + r) * DOUT + d];
    }
    szs[a] = 1.0f;
    if (a == 0) { cnt[0] = 0; cnt[1] = 0; }
    half_bar(h);

    float sq_a = 0.0f;
#pragma unroll
    for (int d = 0; d < DOUT; d++) { float c = centT[d * NPTS + a]; sq_a = fmaf(c, c, sq_a); }
    float s_a = 1.0f;
    int   lab = a;

    for (int t = a; t < NTRI; t += 128) {
        int i = (int)((255.0f - sqrtf(65025.0f - 8.0f * (float)t)) * 0.5f);
        i = i < 0 ? 0 : (i > 126 ? 126 : i);
        while (i > 0   && tri_base(i)     > t) i--;
        while (i < 126 && tri_base(i + 1) <= t) i++;
        int j = i + 1 + (t - tri_base(i));
        float dot = 0.0f, sqi = 0.0f, sqj = 0.0f;
#pragma unroll
        for (int d = 0; d < DOUT; d++) {
            float ci = centT[d * NPTS + i];
            float cj = centT[d * NPTS + j];
            dot = fmaf(ci, cj, dot);
            sqi = fmaf(ci, ci, sqi);
            sqj = fmaf(cj, cj, sqj);
        }
        float d2 = fmaxf(sqi + sqj - 2.0f * dot, 0.0f);
        float w  = (1.0f * 1.0f) / (1.0f + 1.0f + 1e-30f);
        float v  = w * d2;
        D[i * DSTR + j] = v;
        D[j * DSTR + i] = v;
    }
    D[a * DSTR + a] = INF;
    half_bar(h);

    {
        float m = INF; int col = 0;
        const float4* r4 = (const float4*)(D + a * DSTR);
#pragma unroll 8
        for (int q = 0; q < 32; q++) {
            float4 v = r4[q];
            int c0 = q * 4;
            if (v.x < m) { m = v.x; col = c0; }
            if (v.y < m) { m = v.y; col = c0 + 1; }
            if (v.z < m) { m = v.z; col = c0 + 2; }
            if (v.w < m) { m = v.w; col = c0 + 3; }
        }
        Mkey[a] = mkkey(m, a, col);
    }
    half_bar(h);

    // ---- 120 merges ----
    for (int it = 0; it < NPTS - KCL; it++) {
        const int p = it & 1;

        // S1: each warp (of this half) redundantly computes the half's argmin
        ulonglong2 ka = ((const ulonglong2*)Mkey)[lane];
        ulonglong2 kb = ((const ulonglong2*)Mkey)[32 + lane];
        unsigned long long k = umin64(umin64(ka.x, ka.y), umin64(kb.x, kb.y));
#pragma unroll
        for (int off = 16; off; off >>= 1) {
            unsigned long long o = __shfl_down_sync(0xffffffffu, k, off);
            if (o < k) k = o;
        }
        k = __shfl_sync(0xffffffffu, k, 0);
        const int i2 = (int)((k >> 16) & 0xff);
        const int j2 = (int)(k & 0xff);   // mirror symmetry => i2 < j2

        // S2: merged centroid into side buffer
        const float si = szs[i2], sj = szs[j2], snew = si + sj;
        centNew[lane] = (centT[lane * NPTS + i2] * si + centT[lane * NPTS + j2] * sj) / snew;

        // S3: distances to merged cluster; row-min maintenance
        if (a == 0) cnt[p ^ 1] = 0;
        if (lab == j2) lab = i2;
        if (a == j2) { s_a = 0.0f; Mkey[a] = mkkey(INF, a, 0xff); }

        float dot = 0.0f, sqi2 = 0.0f;
#pragma unroll
        for (int d = 0; d < DOUT; d++) {
            float n = centNew[d];
            dot  = fmaf(n, centT[d * NPTS + a], dot);
            sqi2 = fmaf(n, n, sqi2);
        }

        if (a == i2) {
            s_a  = snew;
            sq_a = sqi2;
            int idx = atomicAdd(&cnt[p], 1);
            list[p * NPTS + idx] = a;
        } else {
            float v;
            if (s_a == 0.0f) v = INF;
            else {
                float d2 = fmaxf(sqi2 + sq_a - 2.0f * dot, 0.0f);
                float w  = (snew * s_a) / (snew + s_a + 1e-30f);
                v = w * d2;
            }
            D[a * DSTR + i2] = v;
            D[i2 * DSTR + a] = v;
            if (a != j2) {
                D[a * DSTR + j2] = INF;
                D[j2 * DSTR + a] = INF;
            }
            if (s_a != 0.0f) {
                int myc = (int)(Mkey[a] & 0xffff);
                if (myc == i2 || myc == j2) {
                    int idx = atomicAdd(&cnt[p], 1);
                    list[p * NPTS + idx] = a;
                } else {
                    unsigned long long nk = mkkey(v, a, i2);
                    if (nk < Mkey[a]) Mkey[a] = nk;
                }
            }
        }
        half_bar(h);   // BAR1

        // S4: whole-warp rescans of stale rows; patch centT/szs
        {
            int n = cnt[p];
            int wloc = (tid >> 5) & 3;          // warp index within half
            for (int kk2 = wloc; kk2 < n; kk2 += 4) {
                int r = list[p * NPTS + kk2];
                float4 qv = ((const float4*)(D + r * DSTR))[lane];
                int c0 = 4 * lane;
                unsigned long long kr = mkkey(qv.x, r, c0);
                kr = umin64(kr, mkkey(qv.y, r, c0 + 1));
                kr = umin64(kr, mkkey(qv.z, r, c0 + 2));
                kr = umin64(kr, mkkey(qv.w, r, c0 + 3));
#pragma unroll
                for (int off = 16; off; off >>= 1) {
                    unsigned long long o = __shfl_down_sync(0xffffffffu, kr, off);
                    if (o < kr) kr = o;
                }
                if (lane == 0) Mkey[r] = kr;
            }
            centT[lane * NPTS + i2] = centNew[lane];
            if (a == 0) { szs[i2] = snew; szs[j2] = 0.0f; }
        }
        half_bar(h);   // BAR2
    }

    // ---- rank surviving representatives -> labels (float32 output) ----
    unsigned mball = __ballot_sync(0xffffffffu, s_a > 0.0f);
    if (lane == 0) sAlive[(tid >> 5) & 3] = mball;
    half_bar(h);
    const int r = lab, rw = r >> 5, rl = r & 31;
    int rank = 0;
#pragma unroll
    for (int w4 = 0; w4 < 4; w4++) {
        unsigned mm = sAlive[w4];
        if (w4 < rw)       rank += __popc(mm);
        else if (w4 == rw) rank += __popc(mm & ((rl == 0) ? 0u : (0xffffffffu >> (32 - rl))));
    }
    out[b * NPTS + a] = (float)rank;
}

// ---------------------------------------------------------------------------
extern "C" void kernel_launch(void* const* d_in, const int* in_sizes, int n_in,
                              void* d_out, int out_size) {
    const float* x  = (const float*)d_in[0];
    const float* W1 = (n_in > 1) ? (const float*)d_in[1] : 0;
    const float* b1 = (n_in > 2) ? (const float*)d_in[2] : 0;
    const float* W2 = (n_in > 3) ? (const float*)d_in[3] : 0;
    const float* b2 = (n_in > 4) ? (const float*)d_in[4] : 0;
    for (int i = 0; i < n_in; i++) {
        switch (in_sizes[i]) {
            case BN * DIN:   x  = (const float*)d_in[i]; break;
            case DIN * H1D:  W1 = (const float*)d_in[i]; break;
            case H1D:        b1 = (const float*)d_in[i]; break;
            case H1D * DOUT: W2 = (const float*)d_in[i]; break;
            case DOUT:       b2 = (const float*)d_in[i]; break;
            default: break;
        }
    }
    float* out = (float*)d_out;

    static int smem_set = 0;
    if (!smem_set) {
        cudaFuncSetAttribute(ward_kernel, cudaFuncAttributeMaxDynamicSharedMemorySize,
                             WARD_DYN_SMEM);
        smem_set = 1;
    }

    mlp_kernel<<<BN / 32, 256>>>(x, W1, b1, W2, b2);
    ward_kernel<<<NB / 2, 256, WARD_DYN_SMEM>>>(out);
}

// round 12
// speedup vs baseline: 1.0635x; 1.0635x over previous
#include <cuda_runtime.h>
#include <math.h>

#define NB    128
#define NPTS  128
#define DIN   1024
#define H1D   256
#define DOUT  32
#define KCL   8
#define NTRI  8128
#define BN    16384
#define DSTR  132   // D row stride in floats

__device__ float g_feats[BN * DOUT];

__device__ __forceinline__ float gelu_exact(float v) {
    return 0.5f * v * (1.0f + erff(v * 0.70710678118654752440f));
}
__device__ __forceinline__ int tri_base(int i) { return (i * (255 - i)) >> 1; }

__device__ __forceinline__ unsigned long long pack2(float v) {
    unsigned long long r;
    asm("mov.b64 %0, {%1, %1};" : "=l"(r) : "f"(v));
    return r;
}
__device__ __forceinline__ void fma2(unsigned long long& d, unsigned long long a, unsigned long long b) {
    asm("fma.rn.f32x2 %0, %1, %2, %3;" : "=l"(d) : "l"(a), "l"(b), "l"(d));
}
__device__ __forceinline__ float2 unpack2(unsigned long long v) {
    float2 r;
    asm("mov.b64 {%0, %1}, %2;" : "=f"(r.x), "=f"(r.y) : "l"(v));
    return r;
}

// ---------------------------------------------------------------------------
// MLP: 512 CTAs x 256 threads, 2 CTAs/SM. Double-buffered gelu(x) staging:
// chunk c+1's LDGs are issued BEFORE chunk c's FFMA2 loop (latency hidden),
// erf+STS into the alternate buffer after; ONE barrier per chunk.
// ---------------------------------------------------------------------------
__global__ __launch_bounds__(256, 2) void mlp_kernel(
    const float* __restrict__ x,  const float* __restrict__ W1,
    const float* __restrict__ b1, const float* __restrict__ W2,
    const float* __restrict__ b2)
{
    __shared__ __align__(16) float xs[2][128 * 36];   // 36.9 KB
    const int tid  = threadIdx.x;
    const int tok0 = blockIdx.x * 32;
    const int grp  = tid >> 7;
    const int cp   = tid & 127;

    unsigned long long acc[16];
#pragma unroll
    for (int u = 0; u < 16; u++) acc[u] = 0ull;

    // stage chunk 0
#pragma unroll
    for (int s = 0; s < 16; s++) {
        int idx = tid + s * 256;
        int t = idx >> 7, kk = idx & 127;
        xs[0][kk * 36 + t] = gelu_exact(x[(size_t)(tok0 + t) * DIN + kk]);
    }
    __syncthreads();

    for (int c = 0; c < 8; c++) {
        float xr[16];
        if (c < 7) {
#pragma unroll
            for (int s = 0; s < 16; s++) {
                int idx = tid + s * 256;
                int t = idx >> 7, kk = idx & 127;
                xr[s] = x[(size_t)(tok0 + t) * DIN + (c + 1) * 128 + kk];
            }
        }

        const float* cur = xs[c & 1];
        const float* wp  = W1 + (size_t)(c * 128) * H1D + 2 * cp;
        float2 wv = *(const float2*)wp;
#pragma unroll 4
        for (int kk = 0; kk < 128; kk++) {
            float2 curw = wv;
            if (kk + 1 < 128)
                wv = *(const float2*)(wp + (size_t)(kk + 1) * H1D);
            unsigned long long w0 = pack2(curw.x), w1 = pack2(curw.y);
            const ulonglong2* row = (const ulonglong2*)(cur + kk * 36 + grp * 16);
#pragma unroll
            for (int v = 0; v < 4; v++) {
                ulonglong2 f = row[v];
                fma2(acc[2 * v],         f.x, w0);
                fma2(acc[2 * v + 1],     f.y, w0);
                fma2(acc[8 + 2 * v],     f.x, w1);
                fma2(acc[8 + 2 * v + 1], f.y, w1);
            }
        }

        if (c < 7) {
            float* nxt = xs[(c + 1) & 1];
#pragma unroll
            for (int s = 0; s < 16; s++) {
                int idx = tid + s * 256;
                int t = idx >> 7, kk = idx & 127;
                nxt[kk * 36 + t] = gelu_exact(xr[s]);
            }
        }
        __syncthreads();
    }

    float h0[16], h1[16];
    {
        float bb0 = b1[2 * cp], bb1 = b1[2 * cp + 1];
#pragma unroll
        for (int u = 0; u < 8; u++) {
            float2 p0 = unpack2(acc[u]);
            h0[2 * u]     = gelu_exact(p0.x + bb0);
            h0[2 * u + 1] = gelu_exact(p0.y + bb0);
            float2 p1 = unpack2(acc[8 + u]);
            h1[2 * u]     = gelu_exact(p1.x + bb1);
            h1[2 * u + 1] = gelu_exact(p1.y + bb1);
        }
    }

    // layer 2: stage hidden by halves into xs[0]
    float oacc[4];
#pragma unroll
    for (int u = 0; u < 4; u++) oacc[u] = b2[(u * 256 + tid) & 31];

    float* stage = xs[0];
    for (int half = 0; half < 2; half++) {
        if ((cp >> 6) == half) {
            int c0 = 2 * cp - half * 128;
#pragma unroll
            for (int t = 0; t < 16; t++) {
                stage[(grp * 16 + t) * 128 + c0]     = h0[t];
                stage[(grp * 16 + t) * 128 + c0 + 1] = h1[t];
            }
        }
        __syncthreads();
#pragma unroll
        for (int u = 0; u < 4; u++) {
            int lin = u * 256 + tid;
            int t = lin >> 5, o = lin & 31;
            float s = oacc[u];
            for (int j = 0; j < 128; j++)
                s = fmaf(stage[t * 128 + j], W2[(size_t)(half * 128 + j) * DOUT + o], s);
            oacc[u] = s;
        }
        __syncthreads();
    }
#pragma unroll
    for (int u = 0; u < 4; u++) {
        int lin = u * 256 + tid;
        int t = lin >> 5, o = lin & 31;
        g_feats[(size_t)(tok0 + t) * DOUT + o] = oacc[u];
    }
}

// ---------------------------------------------------------------------------
// Ward: R10-proven design, verbatim. 128 threads/CTA, square D + u64 row-min
// keys in dynamic smem, redundant per-warp argmin, 2 barriers/iteration.
// ---------------------------------------------------------------------------
#define WARD_DYN_SMEM (NPTS*DSTR*4 + DOUT*NPTS*4 + NPTS*8 + NPTS*4 + DOUT*4 + 8 + 2*NPTS*4 + 16)

__device__ __forceinline__ unsigned long long umin64(unsigned long long a, unsigned long long b) {
    return a < b ? a : b;
}
__device__ __forceinline__ unsigned long long mkkey(float v, int row, int col) {
    return ((unsigned long long)__float_as_uint(v) << 32) |
           ((unsigned long long)row << 16) | (unsigned long long)col;
}

__global__ __launch_bounds__(128) void ward_kernel(float* __restrict__ out) {
    extern __shared__ __align__(16) float sm[];
    float* D     = sm;
    float* centT = D + NPTS * DSTR;
    unsigned long long* Mkey = (unsigned long long*)(centT + DOUT * NPTS);
    float* szs     = (float*)(Mkey + NPTS);
    float* centNew = szs + NPTS;
    int*   cnt     = (int*)(centNew + DOUT);
    int*   list    = cnt + 2;

    const int a    = threadIdx.x;
    const int b    = blockIdx.x;
    const int lane = a & 31;
    const int wid  = a >> 5;
    const float INF = __int_as_float(0x7f800000);

    for (int idx = a; idx < NPTS * DOUT; idx += 128) {
        int r = idx >> 5, d = idx & 31;
        centT[d * NPTS + r] = g_feats[(size_t)(b * NPTS + r) * DOUT + d];
    }
    szs[a] = 1.0f;
    if (a == 0) { cnt[0] = 0; cnt[1] = 0; }
    __syncthreads();

    float sq_a = 0.0f;
#pragma unroll
    for (int d = 0; d < DOUT; d++) { float c = centT[d * NPTS + a]; sq_a = fmaf(c, c, sq_a); }
    float s_a = 1.0f;
    int   lab = a;

    for (int t = a; t < NTRI; t += 128) {
        int i = (int)((255.0f - sqrtf(65025.0f - 8.0f * (float)t)) * 0.5f);
        i = i < 0 ? 0 : (i > 126 ? 126 : i);
        while (i > 0   && tri_base(i)     > t) i--;
        while (i < 126 && tri_base(i + 1) <= t) i++;
        int j = i + 1 + (t - tri_base(i));
        float dot = 0.0f, sqi = 0.0f, sqj = 0.0f;
#pragma unroll
        for (int d = 0; d < DOUT; d++) {
            float ci = centT[d * NPTS + i];
            float cj = centT[d * NPTS + j];
            dot = fmaf(ci, cj, dot);
            sqi = fmaf(ci, ci, sqi);
            sqj = fmaf(cj, cj, sqj);
        }
        float d2 = fmaxf(sqi + sqj - 2.0f * dot, 0.0f);
        float w  = (1.0f * 1.0f) / (1.0f + 1.0f + 1e-30f);
        float v  = w * d2;
        D[i * DSTR + j] = v;
        D[j * DSTR + i] = v;
    }
    D[a * DSTR + a] = INF;
    __syncthreads();

    {
        float m = INF; int col = 0;
        const float4* r4 = (const float4*)(D + a * DSTR);
#pragma unroll 8
        for (int q = 0; q < 32; q++) {
            float4 v = r4[q];
            int c0 = q * 4;
            if (v.x < m) { m = v.x; col = c0; }
            if (v.y < m) { m = v.y; col = c0 + 1; }
            if (v.z < m) { m = v.z; col = c0 + 2; }
            if (v.w < m) { m = v.w; col = c0 + 3; }
        }
        Mkey[a] = mkkey(m, a, col);
    }
    __syncthreads();

    for (int it = 0; it < NPTS - KCL; it++) {
        const int p = it & 1;

        ulonglong2 ka = ((const ulonglong2*)Mkey)[lane];
        ulonglong2 kb = ((const ulonglong2*)Mkey)[32 + lane];
        unsigned long long k = umin64(umin64(ka.x, ka.y), umin64(kb.x, kb.y));
#pragma unroll
        for (int off = 16; off; off >>= 1) {
            unsigned long long o = __shfl_down_sync(0xffffffffu, k, off);
            if (o < k) k = o;
        }
        k = __shfl_sync(0xffffffffu, k, 0);
        const int i2 = (int)((k >> 16) & 0xff);
        const int j2 = (int)(k & 0xff);

        const float si = szs[i2], sj = szs[j2], snew = si + sj;
        centNew[lane] = (centT[lane * NPTS + i2] * si + centT[lane * NPTS + j2] * sj) / snew;

        if (a == 0) cnt[p ^ 1] = 0;
        if (lab == j2) lab = i2;
        if (a == j2) { s_a = 0.0f; Mkey[a] = mkkey(INF, a, 0xff); }

        float dot = 0.0f, sqi2 = 0.0f;
#pragma unroll
        for (int d = 0; d < DOUT; d++) {
            float n = centNew[d];
            dot  = fmaf(n, centT[d * NPTS + a], dot);
            sqi2 = fmaf(n, n, sqi2);
        }

        if (a == i2) {
            s_a  = snew;
            sq_a = sqi2;
            int idx = atomicAdd(&cnt[p], 1);
            list[p * NPTS + idx] = a;
        } else {
            float v;
            if (s_a == 0.0f) v = INF;
            else {
                float d2 = fmaxf(sqi2 + sq_a - 2.0f * dot, 0.0f);
                float w  = (snew * s_a) / (snew + s_a + 1e-30f);
                v = w * d2;
            }
            D[a * DSTR + i2] = v;
            D[i2 * DSTR + a] = v;
            if (a != j2) {
                D[a * DSTR + j2] = INF;
                D[j2 * DSTR + a] = INF;
            }
            if (s_a != 0.0f) {
                int myc = (int)(Mkey[a] & 0xffff);
                if (myc == i2 || myc == j2) {
                    int idx = atomicAdd(&cnt[p], 1);
                    list[p * NPTS + idx] = a;
                } else {
                    unsigned long long nk = mkkey(v, a, i2);
                    if (nk < Mkey[a]) Mkey[a] = nk;
                }
            }
        }
        __syncthreads();

        {
            int n = cnt[p];
            for (int kk2 = wid; kk2 < n; kk2 += 4) {
                int r = list[p * NPTS + kk2];
                float4 qv = ((const float4*)(D + r * DSTR))[lane];
                int c0 = 4 * lane;
                unsigned long long kr = mkkey(qv.x, r, c0);
                kr = umin64(kr, mkkey(qv.y, r, c0 + 1));
                kr = umin64(kr, mkkey(qv.z, r, c0 + 2));
                kr = umin64(kr, mkkey(qv.w, r, c0 + 3));
#pragma unroll
                for (int off = 16; off; off >>= 1) {
                    unsigned long long o = __shfl_down_sync(0xffffffffu, kr, off);
                    if (o < kr) kr = o;
                }
                if (lane == 0) Mkey[r] = kr;
            }
            centT[lane * NPTS + i2] = centNew[lane];
            if (a == 0) { szs[i2] = snew; szs[j2] = 0.0f; }
        }
        __syncthreads();
    }

    __shared__ unsigned sAlive[4];
    unsigned mball = __ballot_sync(0xffffffffu, s_a > 0.0f);
    if (lane == 0) sAlive[wid] = mball;
    __syncthreads();
    const int r = lab, rw = r >> 5, rl = r & 31;
    int rank = 0;
#pragma unroll
    for (int w4 = 0; w4 < 4; w4++) {
        unsigned mm = sAlive[w4];
        if (w4 < rw)       rank += __popc(mm);
        else if (w4 == rw) rank += __popc(mm & ((rl == 0) ? 0u : (0xffffffffu >> (32 - rl))));
    }
    out[b * NPTS + a] = (float)rank;
}

// ---------------------------------------------------------------------------
extern "C" void kernel_launch(void* const* d_in, const int* in_sizes, int n_in,
                              void* d_out, int out_size) {
    const float* x  = (const float*)d_in[0];
    const float* W1 = (n_in > 1) ? (const float*)d_in[1] : 0;
    const float* b1 = (n_in > 2) ? (const float*)d_in[2] : 0;
    const float* W2 = (n_in > 3) ? (const float*)d_in[3] : 0;
    const float* b2 = (n_in > 4) ? (const float*)d_in[4] : 0;
    for (int i = 0; i < n_in; i++) {
        switch (in_sizes[i]) {
            case BN * DIN:   x  = (const float*)d_in[i]; break;
            case DIN * H1D:  W1 = (const float*)d_in[i]; break;
            case H1D:        b1 = (const float*)d_in[i]; break;
            case H1D * DOUT: W2 = (const float*)d_in[i]; break;
            case DOUT:       b2 = (const float*)d_in[i]; break;
            default: break;
        }
    }
    float* out = (float*)d_out;

    static int smem_set = 0;
    if (!smem_set) {
        cudaFuncSetAttribute(ward_kernel, cudaFuncAttributeMaxDynamicSharedMemorySize,
                             WARD_DYN_SMEM);
        smem_set = 1;
    }

    mlp_kernel<<<BN / 32, 256>>>(x, W1, b1, W2, b2);
    ward_kernel<<<NB, 128, WARD_DYN_SMEM>>>(out);
}